// round 16
// baseline (speedup 1.0000x reference)
#include <cuda_runtime.h>
#include <math.h>

#define C        144
#define W        77
#define KW       10
#define FC       64
#define CONV_OUT 68                    // W - KW + 1
#define CONCAT   (C*FC + CONV_OUT)     // 9284
#define H2       128
#define GRID     C                     // one block per channel
#define NT       1024
#define PAD      64                    // 256 B accumulator stride (L2 slice spread)

// Scratch (no device allocation allowed); zeroed at load, reset by last block.
__device__ __align__(256) float g_hp[H2 * PAD];
__device__ __align__(256) float g_convp[CONV_OUT * PAD];
__device__ unsigned int g_cnt = 0u;

__device__ __forceinline__ float warp_reduce(float v) {
#pragma unroll
    for (int o = 16; o > 0; o >>= 1) v += __shfl_down_sync(0xffffffffu, v, o);
    return v;
}

__device__ __forceinline__ float group8_reduce(float v) {
#pragma unroll
    for (int o = 4; o > 0; o >>= 1)
        v += __shfl_down_sync(0xffffffffu, v, o, 8);
    return v;
}

__device__ __forceinline__ float dot4(float4 a, float4 b) {
    return a.x * b.x + a.y * b.y + a.z * b.z + a.w * b.w;
}

// ---------------------------------------------------------------------------
// Consolidated best-of kernel.
//   Block c (R9 body): front-batched loads -> early conv REDs (direct x,
//     plain atomicAdd + fence) -> FC (no barrier) -> one __syncthreads ->
//     w2-slice dot -> plain RED into padded g_hp + fence.
//   Last block (R15 slim tail): ONE independent load wave (w2 conv regs,
//     g_convp, g_hp, b2, w3), conv matvec, relu/w3-dot/sigmoid, reset.
// ---------------------------------------------------------------------------
__global__ __launch_bounds__(NT, 1) void fused_kernel(
    const float* __restrict__ x,       // [C, W]
    const float* __restrict__ fc_w,    // [C, FC, W]
    const float* __restrict__ fc_b,    // [C, FC]
    const float* __restrict__ conv_w,  // [C, KW]
    const float* __restrict__ conv_b,  // [1]
    const float* __restrict__ w2,      // [H2, CONCAT]
    const float* __restrict__ b2,      // [H2]
    const float* __restrict__ w3,      // [1, H2]
    const float* __restrict__ b3,      // [1]
    float* __restrict__ out)           // [1]
{
    const int tid  = threadIdx.x;
    const int lane = tid & 31;
    const int warp = tid >> 5;
    const int c    = blockIdx.x;

    const int j = tid >> 3;            // 0..127 : w2 row owned by this thread
    const int p = tid & 7;             // 0..7   : position within row group

    __shared__ __align__(16) float vals[FC];
    __shared__ float sm_h[H2];
    __shared__ unsigned int s_last;

    // =============== front-batched global loads (max MLP) ===============
    const bool tail = (lane < W - 64);                   // 13-element tail

    // (1) w2 FC slice: row j cols [c*64, +64) = 16 float4; 8 th/row, 2 each
    const float4* wrow = reinterpret_cast<const float4*>(
        w2 + (size_t)j * CONCAT + c * FC);
    const float4 a0 = wrow[p];
    const float4 a1 = wrow[p + 8];

    // (2) per-warp x slice (redundant across warps; tiny + L2-hot)
    const float* xr = x + c * W;
    const float x0 = xr[lane];
    const float x1 = xr[lane + 32];
    const float x2 = tail ? xr[lane + 64] : 0.f;

    // (3) fc_w operands for this warp's 2 outputs
    const int d0 = warp * 2;
    const float* r0 = fc_w + (size_t)(c * FC + d0) * W;
    const float* r1 = r0 + W;
    const float f00 = r0[lane], f01 = r0[lane + 32], f02 = tail ? r0[lane + 64] : 0.f;
    const float f10 = r1[lane], f11 = r1[lane + 32], f12 = tail ? r1[lane + 64] : 0.f;

    // ---- conv contribution early: direct x loads (L1 hits), RED, fence ----
    if (tid < CONV_OUT) {
        float s = 0.f;
#pragma unroll
        for (int k = 0; k < KW; k++)
            s += xr[tid + k] * __ldg(&conv_w[c * KW + k]);
        atomicAdd(&g_convp[tid * PAD], s);
        __threadfence();               // release my conv RED
    }

    // =================== FC: no barrier needed ===========================
    {
        float s0 = f00 * x0 + f01 * x1 + f02 * x2;
        float s1 = f10 * x0 + f11 * x1 + f12 * x2;
        s0 = warp_reduce(s0);
        s1 = warp_reduce(s1);
        if (lane == 0) {
            vals[d0]     = s0 + fc_b[c * FC + d0];
            vals[d0 + 1] = s1 + fc_b[c * FC + d0 + 1];
        }
    }

    __syncthreads();                   // vals[] now visible

    // -------------- g_hp[j*PAD] += w2_slice[j,:] . vals ------------------
    {
        const float4* v4 = reinterpret_cast<const float4*>(vals);
        float s = dot4(a0, v4[p]) + dot4(a1, v4[p + 8]);
        s = group8_reduce(s);
        if (p == 0) {
            atomicAdd(&g_hp[j * PAD], s);
            __threadfence();           // release my h RED
        }
    }

    // ---- last-block election (no spinning; non-last blocks exit) --------
    __syncthreads();
    if (tid == 0)
        s_last = (atomicAdd(&g_cnt, 1u) == GRID - 1) ? 1u : 0u;
    __syncthreads();
    if (s_last == 0u) return;

    // ====== finalization (last block only; ONE independent load wave) ====
    __threadfence();                   // acquire all g_hp / g_convp updates

    const float4* rw = reinterpret_cast<const float4*>(
        w2 + (size_t)j * CONCAT + C * FC);               // 16B-aligned
    const float4 rk0 = rw[p];
    const float4 rk1 = rw[p + 8];
    float4 rk2 = make_float4(0.f, 0.f, 0.f, 0.f);
    if (p == 0) rk2 = rw[16];

    const float cb = conv_b[0];
    float cv0[4], cv1[4], cv2[4];
#pragma unroll
    for (int i = 0; i < 4; i++) {
        cv0[i] = g_convp[(p * 4 + i) * PAD] + cb;        // cols p*4 .. p*4+3
        cv1[i] = g_convp[(32 + p * 4 + i) * PAD] + cb;   // cols 32+..
    }
#pragma unroll
    for (int i = 0; i < 4; i++)
        cv2[i] = (p == 0) ? g_convp[(64 + i) * PAD] + cb : 0.f;

    const float hacc = (p == 0) ? g_hp[j * PAD] : 0.f;
    const float bj   = (p == 0) ? b2[j] : 0.f;
    const float wj   = (p == 0) ? w3[j] : 0.f;

    // conv matvec + activation (per-row 8-lane reduce)
    {
        float s = rk0.x * cv0[0] + rk0.y * cv0[1] + rk0.z * cv0[2] + rk0.w * cv0[3]
                + rk1.x * cv1[0] + rk1.y * cv1[1] + rk1.z * cv1[2] + rk1.w * cv1[3];
        if (p == 0)
            s += rk2.x * cv2[0] + rk2.y * cv2[1] + rk2.z * cv2[2] + rk2.w * cv2[3];
        s = group8_reduce(s);
        if (p == 0) {
            sm_h[j] = fmaxf(hacc + s + bj, 0.f) * wj;
            g_hp[j * PAD] = 0.f;       // reset for next replay
        }
    }
    if (tid < CONV_OUT) g_convp[tid * PAD] = 0.f;        // reset
    __syncthreads();

    if (warp == 0) {
        float v = sm_h[lane] + sm_h[lane + 32]
                + sm_h[lane + 64] + sm_h[lane + 96];
        v = warp_reduce(v);
        if (lane == 0) {
            const float o2 = fmaxf(v + b3[0], 0.f);
            out[0] = 1.f / (1.f + __expf(-o2));
            g_cnt = 0u;                // reset for next replay
        }
    }
}

// ---------------------------------------------------------------------------
extern "C" void kernel_launch(void* const* d_in, const int* in_sizes, int n_in,
                              void* d_out, int out_size) {
    const float* x      = (const float*)d_in[0];
    const float* fc_w   = (const float*)d_in[1];
    const float* fc_b   = (const float*)d_in[2];
    const float* conv_w = (const float*)d_in[3];
    const float* conv_b = (const float*)d_in[4];
    const float* w2     = (const float*)d_in[5];
    const float* b2     = (const float*)d_in[6];
    const float* w3     = (const float*)d_in[7];
    const float* b3     = (const float*)d_in[8];

    fused_kernel<<<GRID, NT>>>(x, fc_w, fc_b, conv_w, conv_b,
                               w2, b2, w3, b3, (float*)d_out);
}

// round 17
// speedup vs baseline: 1.1667x; 1.1667x over previous
#include <cuda_runtime.h>
#include <math.h>

#define C        144
#define W        77
#define KW       10
#define FC       64
#define CONV_OUT 68                    // W - KW + 1
#define CONCAT   (C*FC + CONV_OUT)     // 9284
#define H2       128
#define GRID     C                     // one block per channel
#define NT       1024
#define PAD      64                    // 256 B accumulator stride (L2 slice spread)

// Scratch (no device allocation allowed); zeroed at load, reset by last block.
__device__ __align__(256) float g_hp[H2 * PAD];
__device__ __align__(256) float g_convp[CONV_OUT * PAD];
__device__ unsigned int g_cnt = 0u;

__device__ __forceinline__ float warp_reduce(float v) {
#pragma unroll
    for (int o = 16; o > 0; o >>= 1) v += __shfl_down_sync(0xffffffffu, v, o);
    return v;
}

__device__ __forceinline__ float group8_reduce(float v) {
#pragma unroll
    for (int o = 4; o > 0; o >>= 1)
        v += __shfl_down_sync(0xffffffffu, v, o, 8);
    return v;
}

__device__ __forceinline__ float dot4(float4 a, float4 b) {
    return a.x * b.x + a.y * b.y + a.z * b.z + a.w * b.w;
}

// ---------------------------------------------------------------------------
// R15 structure with plain atomics (the best-measured combination of parts).
//   Block c: front-batched loads (w2 slice, x, fc_w) -> FC (no barrier) ->
//     one __syncthreads -> conv RED (from smem xs/cw) + w2-slice dot ->
//     plain REDs into padded scratch -> ONE fence by RED-issuing threads ->
//     election.
//   Last block: ONE independent load wave (w2 conv regs, g_convp, g_hp,
//     b2, w3), conv matvec, relu/w3-dot/sigmoid, scratch reset.
// ---------------------------------------------------------------------------
__global__ __launch_bounds__(NT, 1) void fused_kernel(
    const float* __restrict__ x,       // [C, W]
    const float* __restrict__ fc_w,    // [C, FC, W]
    const float* __restrict__ fc_b,    // [C, FC]
    const float* __restrict__ conv_w,  // [C, KW]
    const float* __restrict__ conv_b,  // [1]
    const float* __restrict__ w2,      // [H2, CONCAT]
    const float* __restrict__ b2,      // [H2]
    const float* __restrict__ w3,      // [1, H2]
    const float* __restrict__ b3,      // [1]
    float* __restrict__ out)           // [1]
{
    const int tid  = threadIdx.x;
    const int lane = tid & 31;
    const int warp = tid >> 5;
    const int c    = blockIdx.x;

    const int j = tid >> 3;            // 0..127 : w2 row owned by this thread
    const int p = tid & 7;             // 0..7   : position within row group

    __shared__ float xs[W];
    __shared__ float cw[KW];
    __shared__ __align__(16) float vals[FC];
    __shared__ float sm_h[H2];
    __shared__ unsigned int s_last;

    // =============== front-batched global loads (max MLP) ===============
    const bool tail = (lane < W - 64);                   // 13-element tail

    // (1) w2 FC slice: row j cols [c*64, +64) = 16 float4; 8 th/row, 2 each
    const float4* wrow = reinterpret_cast<const float4*>(
        w2 + (size_t)j * CONCAT + c * FC);
    const float4 a0 = wrow[p];
    const float4 a1 = wrow[p + 8];

    // (2) per-warp x slice (redundant across warps; tiny + L2-hot)
    const float* xr = x + c * W;
    const float x0 = xr[lane];
    const float x1 = xr[lane + 32];
    const float x2 = tail ? xr[lane + 64] : 0.f;

    // (3) fc_w operands for this warp's 2 outputs
    const int d0 = warp * 2;
    const float* r0 = fc_w + (size_t)(c * FC + d0) * W;
    const float* r1 = r0 + W;
    const float f00 = r0[lane], f01 = r0[lane + 32], f02 = tail ? r0[lane + 64] : 0.f;
    const float f10 = r1[lane], f11 = r1[lane + 32], f12 = tail ? r1[lane + 64] : 0.f;

    // (4) xs / conv weights into smem (consumed after the single barrier)
    if (tid < W)               xs[tid]     = xr[tid];
    else if (tid < W + KW)     cw[tid - W] = conv_w[c * KW + (tid - W)];

    // =================== FC: no barrier needed ===========================
    {
        float s0 = f00 * x0 + f01 * x1 + f02 * x2;
        float s1 = f10 * x0 + f11 * x1 + f12 * x2;
        s0 = warp_reduce(s0);
        s1 = warp_reduce(s1);
        if (lane == 0) {
            vals[d0]     = s0 + fc_b[c * FC + d0];
            vals[d0 + 1] = s1 + fc_b[c * FC + d0 + 1];
        }
    }

    __syncthreads();                   // vals[] and xs[]/cw[] now visible

    // ---------------- conv contribution (plain RED) ----------------------
    if (tid < CONV_OUT) {
        float s = 0.f;
#pragma unroll
        for (int k = 0; k < KW; k++) s += xs[tid + k] * cw[k];
        atomicAdd(&g_convp[tid * PAD], s);
    }

    // -------------- g_hp[j*PAD] += w2_slice[j,:] . vals ------------------
    {
        const float4* v4 = reinterpret_cast<const float4*>(vals);
        float s = dot4(a0, v4[p]) + dot4(a1, v4[p + 8]);
        s = group8_reduce(s);
        if (p == 0) atomicAdd(&g_hp[j * PAD], s);
    }

    // ---- one fence, only in threads that issued REDs, then election -----
    if (p == 0 || tid < CONV_OUT) __threadfence();       // release my REDs
    __syncthreads();
    if (tid == 0)
        s_last = (atomicAdd(&g_cnt, 1u) == GRID - 1) ? 1u : 0u;
    __syncthreads();
    if (s_last == 0u) return;

    // ====== finalization (last block only; ONE independent load wave) ====
    __threadfence();                   // acquire all g_hp / g_convp updates

    const float4* rw = reinterpret_cast<const float4*>(
        w2 + (size_t)j * CONCAT + C * FC);               // 16B-aligned
    const float4 rk0 = rw[p];
    const float4 rk1 = rw[p + 8];
    float4 rk2 = make_float4(0.f, 0.f, 0.f, 0.f);
    if (p == 0) rk2 = rw[16];

    const float cb = conv_b[0];
    float cv0[4], cv1[4], cv2[4];
#pragma unroll
    for (int i = 0; i < 4; i++) {
        cv0[i] = g_convp[(p * 4 + i) * PAD] + cb;        // cols p*4 .. p*4+3
        cv1[i] = g_convp[(32 + p * 4 + i) * PAD] + cb;   // cols 32+..
    }
#pragma unroll
    for (int i = 0; i < 4; i++)
        cv2[i] = (p == 0) ? g_convp[(64 + i) * PAD] + cb : 0.f;

    const float hacc = (p == 0) ? g_hp[j * PAD] : 0.f;
    const float bj   = (p == 0) ? b2[j] : 0.f;
    const float wj   = (p == 0) ? w3[j] : 0.f;

    // conv matvec + activation (per-row 8-lane reduce)
    {
        float s = rk0.x * cv0[0] + rk0.y * cv0[1] + rk0.z * cv0[2] + rk0.w * cv0[3]
                + rk1.x * cv1[0] + rk1.y * cv1[1] + rk1.z * cv1[2] + rk1.w * cv1[3];
        if (p == 0)
            s += rk2.x * cv2[0] + rk2.y * cv2[1] + rk2.z * cv2[2] + rk2.w * cv2[3];
        s = group8_reduce(s);
        if (p == 0) {
            sm_h[j] = fmaxf(hacc + s + bj, 0.f) * wj;
            g_hp[j * PAD] = 0.f;       // reset for next replay
        }
    }
    if (tid < CONV_OUT) g_convp[tid * PAD] = 0.f;        // reset
    __syncthreads();

    if (warp == 0) {
        float v = sm_h[lane] + sm_h[lane + 32]
                + sm_h[lane + 64] + sm_h[lane + 96];
        v = warp_reduce(v);
        if (lane == 0) {
            const float o2 = fmaxf(v + b3[0], 0.f);
            out[0] = 1.f / (1.f + __expf(-o2));
            g_cnt = 0u;                // reset for next replay
        }
    }
}

// ---------------------------------------------------------------------------
extern "C" void kernel_launch(void* const* d_in, const int* in_sizes, int n_in,
                              void* d_out, int out_size) {
    const float* x      = (const float*)d_in[0];
    const float* fc_w   = (const float*)d_in[1];
    const float* fc_b   = (const float*)d_in[2];
    const float* conv_w = (const float*)d_in[3];
    const float* conv_b = (const float*)d_in[4];
    const float* w2     = (const float*)d_in[5];
    const float* b2     = (const float*)d_in[6];
    const float* w3     = (const float*)d_in[7];
    const float* b3     = (const float*)d_in[8];

    fused_kernel<<<GRID, NT>>>(x, fc_w, fc_b, conv_w, conv_b,
                               w2, b2, w3, b3, (float*)d_out);
}